// round 17
// baseline (speedup 1.0000x reference)
#include <cuda_runtime.h>
#include <math.h>

#define BNUM   2
#define SLEN   2048
#define DMODEL 1024
#define NH     16
#define HD     64
#define MTOT   (BNUM * SLEN)   // 4096

typedef unsigned long long u64;

__device__ __forceinline__ u64 pack2(float lo, float hi) {
    u64 r; asm("mov.b64 %0, {%1, %2};" : "=l"(r) : "f"(lo), "f"(hi)); return r;
}
__device__ __forceinline__ u64 dup2(float v) {
    u64 r; asm("mov.b64 %0, {%1, %1};" : "=l"(r) : "f"(v)); return r;
}
__device__ __forceinline__ void ffma2(u64& d, u64 a, u64 b) {
    asm("fma.rn.f32x2 %0, %1, %2, %0;" : "+l"(d) : "l"(a), "l"(b));
}
__device__ __forceinline__ float2 unpack2(u64 v) {
    float2 f; asm("mov.b64 {%0, %1}, %2;" : "=f"(f.x), "=f"(f.y) : "l"(v)); return f;
}

// Scratch (static device globals -- allocation-free)
__device__ float g_q[BNUM * NH * SLEN * HD];   // [b][h][s][dh]
__device__ float g_k[BNUM * NH * SLEN * HD];
__device__ float g_v[BNUM * NH * SLEN * HD];
__device__ float g_o[MTOT * DMODEL];           // [b*s][d] attention output

// ---------------------------------------------------------------------------
// Projection GEMM: C[m][n] = sum_k A[m][k] * W[n][k]
// 128x128 tile, BK=16, 256 threads as 8(ty,m)x32(tx,n).
// Microtile 16m x 4n: a = 8 m-adjacent u64 pairs (broadcast LDS, mov-free),
// b = 4 scalars dup'd. Per k-step: 32 FFMA2 + 4 dup + 5 LDS (78% fma frac).
// ---------------------------------------------------------------------------

// ---------------- QKV projection + fused RoPE --------------------------------
__global__ __launch_bounds__(256, 2) void qkv_proj_kernel(
    const float* __restrict__ x,
    const float* __restrict__ Wq,
    const float* __restrict__ Wk,
    const float* __restrict__ Wv)
{
    __shared__ float As[2][16 * 132];
    __shared__ float Bs[2][16 * 132];

    const int z = blockIdx.z;                    // 0=q 1=k 2=v
    const float* __restrict__ W = (z == 0) ? Wq : ((z == 1) ? Wk : Wv);
    float* __restrict__ Out     = (z == 0) ? g_q : ((z == 1) ? g_k : g_v);

    const int m0 = blockIdx.x * 128;
    const int n0 = blockIdx.y * 128;
    const int tid = threadIdx.x;
    const int tx = tid & 31, ty = tid >> 5;      // compute layout 32(n) x 8(m)
    const int lk = tid & 15, lg = tid >> 4;      // loader layout

    const float* pa0 = x + (size_t)(m0 + 4 * lg) * DMODEL + lk;
    const float* pa1 = x + (size_t)(m0 + 4 * (lg + 16)) * DMODEL + lk;
    const float* pb0 = W + (size_t)(n0 + 4 * lg) * DMODEL + lk;
    const float* pb1 = W + (size_t)(n0 + 4 * (lg + 16)) * DMODEL + lk;

    u64 accp[8][4];   // m-pair p (rows 16ty+2p,+1) x col (4tx+n)
#pragma unroll
    for (int p = 0; p < 8; ++p)
#pragma unroll
        for (int n = 0; n < 4; ++n) accp[p][n] = 0ull;

    float4 ra[2], rb[2];

    // prologue: load k-tile 0
    ra[0].x = pa0[0]; ra[0].y = pa0[DMODEL]; ra[0].z = pa0[2 * DMODEL]; ra[0].w = pa0[3 * DMODEL];
    ra[1].x = pa1[0]; ra[1].y = pa1[DMODEL]; ra[1].z = pa1[2 * DMODEL]; ra[1].w = pa1[3 * DMODEL];
    rb[0].x = pb0[0]; rb[0].y = pb0[DMODEL]; rb[0].z = pb0[2 * DMODEL]; rb[0].w = pb0[3 * DMODEL];
    rb[1].x = pb1[0]; rb[1].y = pb1[DMODEL]; rb[1].z = pb1[2 * DMODEL]; rb[1].w = pb1[3 * DMODEL];
    *(float4*)&As[0][lk * 132 + 4 * lg]        = ra[0];
    *(float4*)&As[0][lk * 132 + 4 * (lg + 16)] = ra[1];
    *(float4*)&Bs[0][lk * 132 + 4 * lg]        = rb[0];
    *(float4*)&Bs[0][lk * 132 + 4 * (lg + 16)] = rb[1];
    __syncthreads();

    for (int kt = 0; kt < DMODEL; kt += 16) {
        const int cur = (kt >> 4) & 1;
        const bool more = (kt + 16) < DMODEL;
        if (more) {
            const float* qa0 = pa0 + kt + 16;
            const float* qa1 = pa1 + kt + 16;
            const float* qb0 = pb0 + kt + 16;
            const float* qb1 = pb1 + kt + 16;
            ra[0].x = qa0[0]; ra[0].y = qa0[DMODEL]; ra[0].z = qa0[2 * DMODEL]; ra[0].w = qa0[3 * DMODEL];
            ra[1].x = qa1[0]; ra[1].y = qa1[DMODEL]; ra[1].z = qa1[2 * DMODEL]; ra[1].w = qa1[3 * DMODEL];
            rb[0].x = qb0[0]; rb[0].y = qb0[DMODEL]; rb[0].z = qb0[2 * DMODEL]; rb[0].w = qb0[3 * DMODEL];
            rb[1].x = qb1[0]; rb[1].y = qb1[DMODEL]; rb[1].z = qb1[2 * DMODEL]; rb[1].w = qb1[3 * DMODEL];
        }
#pragma unroll
        for (int k = 0; k < 16; ++k) {
            float4 a0 = *(const float4*)&As[cur][k * 132 + 16 * ty];
            float4 a1 = *(const float4*)&As[cur][k * 132 + 16 * ty + 4];
            float4 a2 = *(const float4*)&As[cur][k * 132 + 16 * ty + 8];
            float4 a3 = *(const float4*)&As[cur][k * 132 + 16 * ty + 12];
            float4 b  = *(const float4*)&Bs[cur][k * 132 + 4 * tx];
            u64 ap[8];
            ap[0] = pack2(a0.x, a0.y); ap[1] = pack2(a0.z, a0.w);
            ap[2] = pack2(a1.x, a1.y); ap[3] = pack2(a1.z, a1.w);
            ap[4] = pack2(a2.x, a2.y); ap[5] = pack2(a2.z, a2.w);
            ap[6] = pack2(a3.x, a3.y); ap[7] = pack2(a3.z, a3.w);
            u64 bd[4];
            bd[0] = dup2(b.x); bd[1] = dup2(b.y); bd[2] = dup2(b.z); bd[3] = dup2(b.w);
#pragma unroll
            for (int p = 0; p < 8; ++p) {
                ffma2(accp[p][0], ap[p], bd[0]);
                ffma2(accp[p][1], ap[p], bd[1]);
                ffma2(accp[p][2], ap[p], bd[2]);
                ffma2(accp[p][3], ap[p], bd[3]);
            }
        }
        if (more) {
            const int nxt = cur ^ 1;
            *(float4*)&As[nxt][lk * 132 + 4 * lg]        = ra[0];
            *(float4*)&As[nxt][lk * 132 + 4 * (lg + 16)] = ra[1];
            *(float4*)&Bs[nxt][lk * 132 + 4 * lg]        = rb[0];
            *(float4*)&Bs[nxt][lk * 132 + 4 * (lg + 16)] = rb[1];
            __syncthreads();
        }
    }

    // Epilogue: scatter to [b][h][s][dh]; RoPE for q,k.
    const int ncol = n0 + 4 * tx;            // 4-aligned model column
    const int h    = ncol >> 6;
    const int dh0  = ncol & 63;
    float inv0 = 0.f, inv1 = 0.f;
    if (z < 2) {
        const float L2T = 13.287712379549449f;   // log2(10000)
        inv0 = exp2f(-(float)(dh0)     * (1.0f / 64.0f) * L2T);
        inv1 = exp2f(-(float)(dh0 + 2) * (1.0f / 64.0f) * L2T);
    }
#pragma unroll
    for (int p = 0; p < 8; ++p) {
        float2 c0v = unpack2(accp[p][0]);
        float2 c1v = unpack2(accp[p][1]);
        float2 c2v = unpack2(accp[p][2]);
        float2 c3v = unpack2(accp[p][3]);
        float rowv[2][4] = {{c0v.x, c1v.x, c2v.x, c3v.x},
                            {c0v.y, c1v.y, c2v.y, c3v.y}};
#pragma unroll
        for (int r = 0; r < 2; ++r) {
            int m  = m0 + 16 * ty + 2 * p + r;
            int s  = m & (SLEN - 1);
            int bi = m >> 11;
            float* op = Out + (((size_t)(bi * NH + h) * SLEN + s) * HD + dh0);
            float4 o;
            if (z < 2) {
                float c0, s0, c1, s1;
                sincosf((float)s * inv0, &s0, &c0);
                sincosf((float)s * inv1, &s1, &c1);
                o.x = rowv[r][0] * c0 - rowv[r][1] * s0;
                o.y = rowv[r][0] * s0 + rowv[r][1] * c0;
                o.z = rowv[r][2] * c1 - rowv[r][3] * s1;
                o.w = rowv[r][2] * s1 + rowv[r][3] * c1;
            } else {
                o.x = rowv[r][0]; o.y = rowv[r][1]; o.z = rowv[r][2]; o.w = rowv[r][3];
            }
            *(float4*)op = o;
        }
    }
}

// ---------------------------------------------------------------------------
// Flash attention: block = (64-row q-tile, one bh). 256 threads = 16tx x 16ty.
// BK=128. Microtile QK 4q x 8k (k-pairs). PV 4q x 4d (d-pairs).
// Qs: [d=64][q=64] stride 68; Ks: [d=64][k=128] stride 132;
// Vs: [k=128][d=64] stride 68; Ps ALIASES Ks (P written after QK reads done).
// smem = (64*68 + 64*132 + 128*68)*4 = 86016 B  -> 2 CTAs/SM.
// ---------------------------------------------------------------------------
#define ATTN_SMEM ((64 * 68 + 64 * 132 + 128 * 68) * 4)

__global__ __launch_bounds__(256, 2) void attn_kernel()
{
    extern __shared__ float sm[];
    float* Qs = sm;                    // 64*68
    float* Ks = Qs + 64 * 68;          // 64*132
    float* Vs = Ks + 64 * 132;         // 128*68
    float* Ps = Ks;                    // alias: P overwrites K after QK

    const int bh = blockIdx.y;
    const int qt = (gridDim.x - 1) - blockIdx.x;   // heavy q-tiles first
    const int q0 = qt * 64;
    const float* __restrict__ qb = g_q + (size_t)bh * SLEN * HD;
    const float* __restrict__ kb = g_k + (size_t)bh * SLEN * HD;
    const float* __restrict__ vb = g_v + (size_t)bh * SLEN * HD;

    const int tid = threadIdx.x;
    const int tx = tid & 15, ty = tid >> 4;
    const int d  = tid & 63, g4 = tid >> 6;     // transposed-loader coords
    const int fr = tid >> 4, fc = tid & 15;     // V-loader coords

    // Load Q tile transposed + pre-scaled: Qs[d][q] = Q * 0.125
#pragma unroll
    for (int it = 0; it < 4; ++it) {
        int grp = it * 4 + g4;                   // 0..15 -> q rows 4grp..4grp+3
        const float* qp = qb + (size_t)(q0 + 4 * grp) * HD + d;
        float4 v;
        v.x = qp[0] * 0.125f;       v.y = qp[HD] * 0.125f;
        v.z = qp[2 * HD] * 0.125f;  v.w = qp[3 * HD] * 0.125f;
        *(float4*)&Qs[d * 68 + 4 * grp] = v;
    }

    float m_i[4], l_i[4];
    u64 accp[4][2];                     // q rows 4ty+i, d-col pairs at 4tx
#pragma unroll
    for (int i = 0; i < 4; ++i) {
        m_i[i] = -1e30f; l_i[i] = 0.f;
        accp[i][0] = 0ull; accp[i][1] = 0ull;
    }
    __syncthreads();

    const int lastkt = qt >> 1;        // BK = 2*BQ
    for (int kt = 0; kt <= lastkt; ++kt) {
        const int k0 = kt * 128;
        // K tile transposed: Ks[d][k]  (overwrites previous P; sync'd)
#pragma unroll
        for (int it = 0; it < 8; ++it) {
            int grp = it * 4 + g4;               // 0..31 -> k rows 4grp..4grp+3
            const float* kp = kb + (size_t)(k0 + 4 * grp) * HD + d;
            float4 v;
            v.x = kp[0]; v.y = kp[HD]; v.z = kp[2 * HD]; v.w = kp[3 * HD];
            *(float4*)&Ks[d * 132 + 4 * grp] = v;
        }
        // V tile natural: Vs[k][d]
#pragma unroll
        for (int it = 0; it < 8; ++it) {
            int r = fr + 16 * it;
            *(float4*)&Vs[r * 68 + 4 * fc] =
                *(const float4*)&vb[(size_t)(k0 + r) * HD + 4 * fc];
        }
        __syncthreads();

        // ---- scores: rows 4ty+i, k-pairs (8tx+2jp, 8tx+2jp+1) ----
        u64 scp[4][4];
#pragma unroll
        for (int i = 0; i < 4; ++i)
#pragma unroll
            for (int jp = 0; jp < 4; ++jp) scp[i][jp] = 0ull;

#pragma unroll 4
        for (int dd = 0; dd < 64; ++dd) {
            float4 qv  = *(const float4*)&Qs[dd * 68 + 4 * ty];       // broadcast
            float4 k0f = *(const float4*)&Ks[dd * 132 + 8 * tx];
            float4 k1f = *(const float4*)&Ks[dd * 132 + 8 * tx + 4];
            u64 kp2[4];
            kp2[0] = pack2(k0f.x, k0f.y); kp2[1] = pack2(k0f.z, k0f.w);
            kp2[2] = pack2(k1f.x, k1f.y); kp2[3] = pack2(k1f.z, k1f.w);
            float qa[4] = {qv.x, qv.y, qv.z, qv.w};
#pragma unroll
            for (int i = 0; i < 4; ++i) {
                u64 qd = dup2(qa[i]);
                ffma2(scp[i][0], qd, kp2[0]);
                ffma2(scp[i][1], qd, kp2[1]);
                ffma2(scp[i][2], qd, kp2[2]);
                ffma2(scp[i][3], qd, kp2[3]);
            }
        }
        __syncthreads();   // all QK reads of Ks complete before P overwrites it

        // unpack to scalars for mask + softmax
        float sc[4][8];
#pragma unroll
        for (int i = 0; i < 4; ++i)
#pragma unroll
            for (int jp = 0; jp < 4; ++jp) {
                float2 f = unpack2(scp[i][jp]);
                sc[i][2 * jp] = f.x; sc[i][2 * jp + 1] = f.y;
            }

        // causal mask (last k-tile only): global k > global q
        if (kt == lastkt) {
#pragma unroll
            for (int i = 0; i < 4; ++i)
#pragma unroll
                for (int j = 0; j < 8; ++j)
                    if ((k0 + 8 * tx + j) > (q0 + 4 * ty + i)) sc[i][j] = -1e30f;
        }

        // ---- online softmax (row stats shared by the 16-lane half-warp) ----
#pragma unroll
        for (int i = 0; i < 4; ++i) {
            float mx = sc[i][0];
#pragma unroll
            for (int j = 1; j < 8; ++j) mx = fmaxf(mx, sc[i][j]);
#pragma unroll
            for (int off = 8; off > 0; off >>= 1)
                mx = fmaxf(mx, __shfl_xor_sync(0xffffffffu, mx, off, 16));
            float mnew = fmaxf(m_i[i], mx);
            float corr = __expf(m_i[i] - mnew);
            m_i[i] = mnew;
            float rs = 0.f;
#pragma unroll
            for (int j = 0; j < 8; ++j) {
                float p = __expf(sc[i][j] - mnew);
                sc[i][j] = p;
                rs += p;
            }
#pragma unroll
            for (int off = 8; off > 0; off >>= 1)
                rs += __shfl_xor_sync(0xffffffffu, rs, off, 16);
            l_i[i] = l_i[i] * corr + rs;
            u64 cd = dup2(corr);
            {
                u64 t0 = accp[i][0], t1 = accp[i][1];
                accp[i][0] = 0ull; accp[i][1] = 0ull;
                ffma2(accp[i][0], cd, t0);
                ffma2(accp[i][1], cd, t1);
            }
            // P row -> smem (aliases Ks region: 64 rows x stride 132)
            *(float4*)&Ps[(4 * ty + i) * 132 + 8 * tx] =
                make_float4(sc[i][0], sc[i][1], sc[i][2], sc[i][3]);
            *(float4*)&Ps[(4 * ty + i) * 132 + 8 * tx + 4] =
                make_float4(sc[i][4], sc[i][5], sc[i][6], sc[i][7]);
        }
        __syncthreads();

        // ---- O += P @ V  (rows 4ty+i, d-col pairs at 4tx) ----
#pragma unroll 2
        for (int kk4 = 0; kk4 < 32; ++kk4) {
            u64 vp[4][2];
#pragma unroll
            for (int c = 0; c < 4; ++c) {
                float4 vv = *(const float4*)&Vs[(4 * kk4 + c) * 68 + 4 * tx];
                vp[c][0] = pack2(vv.x, vv.y);
                vp[c][1] = pack2(vv.z, vv.w);
            }
#pragma unroll
            for (int i = 0; i < 4; ++i) {
                float4 p = *(const float4*)&Ps[(4 * ty + i) * 132 + 4 * kk4];
                u64 p0 = dup2(p.x), p1 = dup2(p.y), p2 = dup2(p.z), p3 = dup2(p.w);
                ffma2(accp[i][0], p0, vp[0][0]); ffma2(accp[i][1], p0, vp[0][1]);
                ffma2(accp[i][0], p1, vp[1][0]); ffma2(accp[i][1], p1, vp[1][1]);
                ffma2(accp[i][0], p2, vp[2][0]); ffma2(accp[i][1], p2, vp[2][1]);
                ffma2(accp[i][0], p3, vp[3][0]); ffma2(accp[i][1], p3, vp[3][1]);
            }
        }
        __syncthreads();
    }

    // Normalize and write back to [b][s][h*64+dh]
    const int b_ = bh >> 4, h = bh & 15;
#pragma unroll
    for (int i = 0; i < 4; ++i) {
        int s = q0 + 4 * ty + i;
        float inv = 1.0f / l_i[i];
        float2 f0 = unpack2(accp[i][0]);
        float2 f1 = unpack2(accp[i][1]);
        float4 o = make_float4(f0.x * inv, f0.y * inv, f1.x * inv, f1.y * inv);
        *(float4*)&g_o[((size_t)(b_ * SLEN + s)) * DMODEL + h * HD + 4 * tx] = o;
    }
}

// ---------------------------------------------------------------------------
// Output projection: out[m][n] = sum_k g_o[m][k] * Wo[n][k]
// Same 128x128 tile, 16m(8 pairs) x 4n microtile, double-buffered.
// ---------------------------------------------------------------------------
__global__ __launch_bounds__(256, 2) void out_proj_kernel(
    const float* __restrict__ Wo, float* __restrict__ out)
{
    __shared__ float As[2][16 * 132];
    __shared__ float Bs[2][16 * 132];

    const int m0 = blockIdx.x * 128;
    const int n0 = blockIdx.y * 128;
    const int tid = threadIdx.x;
    const int tx = tid & 31, ty = tid >> 5;
    const int lk = tid & 15, lg = tid >> 4;

    const float* pa0 = g_o + (size_t)(m0 + 4 * lg) * DMODEL + lk;
    const float* pa1 = g_o + (size_t)(m0 + 4 * (lg + 16)) * DMODEL + lk;
    const float* pb0 = Wo + (size_t)(n0 + 4 * lg) * DMODEL + lk;
    const float* pb1 = Wo + (size_t)(n0 + 4 * (lg + 16)) * DMODEL + lk;

    u64 accp[8][4];
#pragma unroll
    for (int p = 0; p < 8; ++p)
#pragma unroll
        for (int n = 0; n < 4; ++n) accp[p][n] = 0ull;

    float4 ra[2], rb[2];
    ra[0].x = pa0[0]; ra[0].y = pa0[DMODEL]; ra[0].z = pa0[2 * DMODEL]; ra[0].w = pa0[3 * DMODEL];
    ra[1].x = pa1[0]; ra[1].y = pa1[DMODEL]; ra[1].z = pa1[2 * DMODEL]; ra[1].w = pa1[3 * DMODEL];
    rb[0].x = pb0[0]; rb[0].y = pb0[DMODEL]; rb[0].z = pb0[2 * DMODEL]; rb[0].w = pb0[3 * DMODEL];
    rb[1].x = pb1[0]; rb[1].y = pb1[DMODEL]; rb[1].z = pb1[2 * DMODEL]; rb[1].w = pb1[3 * DMODEL];
    *(float4*)&As[0][lk * 132 + 4 * lg]        = ra[0];
    *(float4*)&As[0][lk * 132 + 4 * (lg + 16)] = ra[1];
    *(float4*)&Bs[0][lk * 132 + 4 * lg]        = rb[0];
    *(float4*)&Bs[0][lk * 132 + 4 * (lg + 16)] = rb[1];
    __syncthreads();

    for (int kt = 0; kt < DMODEL; kt += 16) {
        const int cur = (kt >> 4) & 1;
        const bool more = (kt + 16) < DMODEL;
        if (more) {
            const float* qa0 = pa0 + kt + 16;
            const float* qa1 = pa1 + kt + 16;
            const float* qb0 = pb0 + kt + 16;
            const float* qb1 = pb1 + kt + 16;
            ra[0].x = qa0[0]; ra[0].y = qa0[DMODEL]; ra[0].z = qa0[2 * DMODEL]; ra[0].w = qa0[3 * DMODEL];
            ra[1].x = qa1[0]; ra[1].y = qa1[DMODEL]; ra[1].z = qa1[2 * DMODEL]; ra[1].w = qa1[3 * DMODEL];
            rb[0].x = qb0[0]; rb[0].y = qb0[DMODEL]; rb[0].z = qb0[2 * DMODEL]; rb[0].w = qb0[3 * DMODEL];
            rb[1].x = qb1[0]; rb[1].y = qb1[DMODEL]; rb[1].z = qb1[2 * DMODEL]; rb[1].w = qb1[3 * DMODEL];
        }
#pragma unroll
        for (int k = 0; k < 16; ++k) {
            float4 a0 = *(const float4*)&As[cur][k * 132 + 16 * ty];
            float4 a1 = *(const float4*)&As[cur][k * 132 + 16 * ty + 4];
            float4 a2 = *(const float4*)&As[cur][k * 132 + 16 * ty + 8];
            float4 a3 = *(const float4*)&As[cur][k * 132 + 16 * ty + 12];
            float4 b  = *(const float4*)&Bs[cur][k * 132 + 4 * tx];
            u64 ap[8];
            ap[0] = pack2(a0.x, a0.y); ap[1] = pack2(a0.z, a0.w);
            ap[2] = pack2(a1.x, a1.y); ap[3] = pack2(a1.z, a1.w);
            ap[4] = pack2(a2.x, a2.y); ap[5] = pack2(a2.z, a2.w);
            ap[6] = pack2(a3.x, a3.y); ap[7] = pack2(a3.z, a3.w);
            u64 bd[4];
            bd[0] = dup2(b.x); bd[1] = dup2(b.y); bd[2] = dup2(b.z); bd[3] = dup2(b.w);
#pragma unroll
            for (int p = 0; p < 8; ++p) {
                ffma2(accp[p][0], ap[p], bd[0]);
                ffma2(accp[p][1], ap[p], bd[1]);
                ffma2(accp[p][2], ap[p], bd[2]);
                ffma2(accp[p][3], ap[p], bd[3]);
            }
        }
        if (more) {
            const int nxt = cur ^ 1;
            *(float4*)&As[nxt][lk * 132 + 4 * lg]        = ra[0];
            *(float4*)&As[nxt][lk * 132 + 4 * (lg + 16)] = ra[1];
            *(float4*)&Bs[nxt][lk * 132 + 4 * lg]        = rb[0];
            *(float4*)&Bs[nxt][lk * 132 + 4 * (lg + 16)] = rb[1];
            __syncthreads();
        }
    }

#pragma unroll
    for (int p = 0; p < 8; ++p) {
        float2 c0v = unpack2(accp[p][0]);
        float2 c1v = unpack2(accp[p][1]);
        float2 c2v = unpack2(accp[p][2]);
        float2 c3v = unpack2(accp[p][3]);
        int mlo = m0 + 16 * ty + 2 * p;
        *(float4*)&out[(size_t)mlo * DMODEL + n0 + 4 * tx] =
            make_float4(c0v.x, c1v.x, c2v.x, c3v.x);
        *(float4*)&out[(size_t)(mlo + 1) * DMODEL + n0 + 4 * tx] =
            make_float4(c0v.y, c1v.y, c2v.y, c3v.y);
    }
}

// ---------------------------------------------------------------------------
extern "C" void kernel_launch(void* const* d_in, const int* in_sizes, int n_in,
                              void* d_out, int out_size)
{
    const float* x  = (const float*)d_in[0];
    const float* Wq = (const float*)d_in[1];
    const float* Wk = (const float*)d_in[2];
    const float* Wv = (const float*)d_in[3];
    const float* Wo = (const float*)d_in[4];
    float* out = (float*)d_out;

    cudaFuncSetAttribute(attn_kernel,
                         cudaFuncAttributeMaxDynamicSharedMemorySize, ATTN_SMEM);

    dim3 gp(MTOT / 128, DMODEL / 128, 3);
    qkv_proj_kernel<<<gp, 256>>>(x, Wq, Wk, Wv);

    dim3 ga(SLEN / 64, BNUM * NH);
    attn_kernel<<<ga, 256, ATTN_SMEM>>>();

    dim3 go(MTOT / 128, DMODEL / 128);
    out_proj_kernel<<<go, 256>>>(Wo, out);
}